// round 1
// baseline (speedup 1.0000x reference)
#include <cuda_runtime.h>

#define C_DIM 256
#define K_CODES 8192
#define N_VEC 16384
#define HW 1024       // H*W
#define CHW 262144    // C*H*W

// Device-global scratch (no allocations allowed in kernel_launch)
__device__ float g_embT[C_DIM * K_CODES];   // [c][k]
__device__ float g_enorm[K_CODES];
__device__ int   g_argmin[N_VEC];

// ---------------------------------------------------------------------------
// Prep: transpose emb [K,C] -> embT [C,K] so the GEMM can load both operands
// c-major with conflict-free smem stores.
// ---------------------------------------------------------------------------
__global__ void prep_transpose_kernel(const float* __restrict__ emb) {
    __shared__ float tile[32][33];
    int kb = blockIdx.x * 32;
    int cb = blockIdx.y * 32;
    int tx = threadIdx.x, ty = threadIdx.y; // 32 x 8
#pragma unroll
    for (int j = 0; j < 4; j++)
        tile[ty + j * 8][tx] = emb[(kb + ty + j * 8) * C_DIM + cb + tx];
    __syncthreads();
#pragma unroll
    for (int j = 0; j < 4; j++)
        g_embT[(cb + ty + j * 8) * K_CODES + kb + tx] = tile[tx][ty + j * 8];
}

// Row norms ||e_k||^2 (one warp per code)
__global__ void enorm_kernel(const float* __restrict__ emb) {
    int k = blockIdx.x * 8 + threadIdx.y;       // block (32,8)
    const float* row = emb + k * C_DIM;
    float s = 0.f;
    for (int c = threadIdx.x; c < C_DIM; c += 32) {
        float v = row[c];
        s += v * v;
    }
#pragma unroll
    for (int o = 16; o; o >>= 1) s += __shfl_xor_sync(0xffffffffu, s, o);
    if (threadIdx.x == 0) g_enorm[k] = s;
}

// ---------------------------------------------------------------------------
// Main: fused GEMM (dot(z_n, e_k)) + running argmin over k of
// d = ||e||^2 - 2*dot  (||z||^2 is constant per row, irrelevant for argmin).
// Block tile: 64 rows x 128 codes, c-chunks of 32. Thread tile 4x8.
// ---------------------------------------------------------------------------
#define BN 64
#define BK 128
#define CC 32

__global__ __launch_bounds__(256) void argmin_kernel(const float* __restrict__ z) {
    __shared__ float zs[CC][BN];
    __shared__ float es[CC][BK];
    __shared__ float red_min[BN][16];
    __shared__ int   red_idx[BN][16];

    int tid = threadIdx.x;
    int tx = tid & 15;   // 16 col-groups
    int ty = tid >> 4;   // 16 row-groups

    int n0 = blockIdx.x * BN;          // 64-aligned, stays within one batch b
    int b  = n0 / HW;
    int p0 = n0 % HW;
    const float* zb = z + (size_t)b * CHW + p0;  // element (c, n) at zb[c*HW + n]

    float rmin[4];
    int   ridx[4];
#pragma unroll
    for (int i = 0; i < 4; i++) { rmin[i] = 3.4e38f; ridx[i] = 0; }

    for (int k0 = 0; k0 < K_CODES; k0 += BK) {
        float acc[4][8];
#pragma unroll
        for (int i = 0; i < 4; i++)
#pragma unroll
            for (int j = 0; j < 8; j++) acc[i][j] = 0.f;

        for (int c0 = 0; c0 < C_DIM; c0 += CC) {
            // load z tile: 32 x 64 floats = 512 float4 (2 per thread), coalesced
#pragma unroll
            for (int u = 0; u < 2; u++) {
                int idx = tid + u * 256;     // 0..511
                int c = idx >> 4;            // 16 float4 per row
                int n4 = idx & 15;
                *(float4*)&zs[c][n4 * 4] =
                    *(const float4*)&zb[(c0 + c) * HW + n4 * 4];
            }
            // load e tile: 32 x 128 floats = 1024 float4 (4 per thread), coalesced
#pragma unroll
            for (int u = 0; u < 4; u++) {
                int idx = tid + u * 256;     // 0..1023
                int c = idx >> 5;            // 32 float4 per row
                int k4 = idx & 31;
                *(float4*)&es[c][k4 * 4] =
                    *(const float4*)&g_embT[(c0 + c) * K_CODES + k0 + k4 * 4];
            }
            __syncthreads();

#pragma unroll
            for (int cc = 0; cc < CC; cc++) {
                float4 zf = *(float4*)&zs[cc][ty * 4];
                float4 e0 = *(float4*)&es[cc][tx * 4];
                float4 e1 = *(float4*)&es[cc][tx * 4 + 64];
                float zz[4] = {zf.x, zf.y, zf.z, zf.w};
                float ee[8] = {e0.x, e0.y, e0.z, e0.w, e1.x, e1.y, e1.z, e1.w};
#pragma unroll
                for (int i = 0; i < 4; i++)
#pragma unroll
                    for (int j = 0; j < 8; j++)
                        acc[i][j] += zz[i] * ee[j];
            }
            __syncthreads();
        }

        // distances + running argmin (ascending k within thread -> '<' keeps
        // the lowest index on exact ties, matching argmin semantics)
#pragma unroll
        for (int j = 0; j < 8; j++) {
            int co = (j < 4) ? (tx * 4 + j) : (tx * 4 + 64 + (j - 4));
            int k = k0 + co;
            float en = __ldg(&g_enorm[k]);
#pragma unroll
            for (int i = 0; i < 4; i++) {
                float d = en - 2.f * acc[i][j];
                if (d < rmin[i]) { rmin[i] = d; ridx[i] = k; }
            }
        }
    }

    // cross-thread reduction (16 col-groups share each row); tie -> lower idx
#pragma unroll
    for (int i = 0; i < 4; i++) {
        red_min[ty * 4 + i][tx] = rmin[i];
        red_idx[ty * 4 + i][tx] = ridx[i];
    }
    __syncthreads();
    if (tid < BN) {
        float m = red_min[tid][0];
        int mi  = red_idx[tid][0];
#pragma unroll
        for (int t = 1; t < 16; t++) {
            float v = red_min[tid][t];
            int vi  = red_idx[tid][t];
            if (v < m || (v == m && vi < mi)) { m = v; mi = vi; }
        }
        g_argmin[n0 + tid] = mi;
    }
}

// ---------------------------------------------------------------------------
// Gather: out[b,c,h,w] = emb[argmin[n]][c], n = b*HW + h*W + w.
// Coalesced float4 writes; emb reads hit L2 (emb is 8.4MB, fully resident).
// ---------------------------------------------------------------------------
__global__ void gather_kernel(const float* __restrict__ emb,
                              float* __restrict__ out) {
    int t = blockIdx.x * blockDim.x + threadIdx.x;  // over N*C/4 float4s
    int p4 = t & 255;
    int c  = (t >> 8) & 255;
    int b  = t >> 16;
    int nb = b * HW + p4 * 4;
    float4 o;
    o.x = __ldg(&emb[g_argmin[nb + 0] * C_DIM + c]);
    o.y = __ldg(&emb[g_argmin[nb + 1] * C_DIM + c]);
    o.z = __ldg(&emb[g_argmin[nb + 2] * C_DIM + c]);
    o.w = __ldg(&emb[g_argmin[nb + 3] * C_DIM + c]);
    ((float4*)out)[t] = o;
}

extern "C" void kernel_launch(void* const* d_in, const int* in_sizes, int n_in,
                              void* d_out, int out_size) {
    (void)in_sizes; (void)n_in; (void)out_size;
    const float* z   = (const float*)d_in[0];
    const float* emb = (const float*)d_in[1];
    float* out = (float*)d_out;

    prep_transpose_kernel<<<dim3(K_CODES / 32, C_DIM / 32), dim3(32, 8)>>>(emb);
    enorm_kernel<<<K_CODES / 8, dim3(32, 8)>>>(emb);
    argmin_kernel<<<N_VEC / BN, 256>>>(z);
    gather_kernel<<<(N_VEC * C_DIM / 4) / 256, 256>>>(emb, out);
}

// round 2
// speedup vs baseline: 1.0044x; 1.0044x over previous
#include <cuda_runtime.h>

#define C_DIM 256
#define K_CODES 8192
#define N_VEC 16384
#define HW 1024       // H*W
#define CHW 262144    // C*H*W

typedef unsigned long long u64;

// Device-global scratch (no allocations allowed in kernel_launch)
__device__ float g_embT[C_DIM * K_CODES];   // [c][k]
__device__ float g_enorm[K_CODES];
__device__ int   g_argmin[N_VEC];

// ---------------- packed f32x2 helpers (Blackwell FFMA2 path) ----------------
__device__ __forceinline__ u64 pack2(float lo, float hi) {
    u64 r;
    asm("mov.b64 %0, {%1, %2};" : "=l"(r) : "f"(lo), "f"(hi));
    return r;
}
__device__ __forceinline__ void unpack2(u64 v, float& lo, float& hi) {
    asm("mov.b64 {%0, %1}, %2;" : "=f"(lo), "=f"(hi) : "l"(v));
}
// acc += a * b   (elementwise on packed f32 pairs)
__device__ __forceinline__ void ffma2_acc(u64& acc, u64 a, u64 b) {
    asm("fma.rn.f32x2 %0, %1, %2, %0;" : "+l"(acc) : "l"(a), "l"(b));
}
// d = a * b + c
__device__ __forceinline__ u64 ffma2(u64 a, u64 b, u64 c) {
    u64 d;
    asm("fma.rn.f32x2 %0, %1, %2, %3;" : "=l"(d) : "l"(a), "l"(b), "l"(c));
    return d;
}

// ---------------------------------------------------------------------------
// Prep: transpose emb [K,C] -> embT [C,K]
// ---------------------------------------------------------------------------
__global__ void prep_transpose_kernel(const float* __restrict__ emb) {
    __shared__ float tile[32][33];
    int kb = blockIdx.x * 32;
    int cb = blockIdx.y * 32;
    int tx = threadIdx.x, ty = threadIdx.y; // 32 x 8
#pragma unroll
    for (int j = 0; j < 4; j++)
        tile[ty + j * 8][tx] = emb[(kb + ty + j * 8) * C_DIM + cb + tx];
    __syncthreads();
#pragma unroll
    for (int j = 0; j < 4; j++)
        g_embT[(cb + ty + j * 8) * K_CODES + kb + tx] = tile[tx][ty + j * 8];
}

// Row norms ||e_k||^2 (one warp per code)
__global__ void enorm_kernel(const float* __restrict__ emb) {
    int k = blockIdx.x * 8 + threadIdx.y;       // block (32,8)
    const float* row = emb + k * C_DIM;
    float s = 0.f;
    for (int c = threadIdx.x; c < C_DIM; c += 32) {
        float v = row[c];
        s += v * v;
    }
#pragma unroll
    for (int o = 16; o; o >>= 1) s += __shfl_xor_sync(0xffffffffu, s, o);
    if (threadIdx.x == 0) g_enorm[k] = s;
}

// ---------------------------------------------------------------------------
// Main: fused GEMM + running argmin over k of d = ||e||^2 - 2*dot.
// Block tile: 64 rows x 128 codes, c-chunks of 32. Thread tile 4x8.
// Inner product done with packed fma.rn.f32x2 (FFMA2): accumulators packed
// along the code axis so e-pairs come straight from the LDS.128 quads.
// ---------------------------------------------------------------------------
#define BN 64
#define BK 128
#define CC 32

__global__ __launch_bounds__(256) void argmin_kernel(const float* __restrict__ z) {
    __shared__ float zs[CC][BN];
    __shared__ float es[CC][BK];
    __shared__ float red_min[BN][16];
    __shared__ int   red_idx[BN][16];

    int tid = threadIdx.x;
    int tx = tid & 15;   // 16 col-groups
    int ty = tid >> 4;   // 16 row-groups

    int n0 = blockIdx.x * BN;          // 64-aligned, stays within one batch b
    int b  = n0 / HW;
    int p0 = n0 % HW;
    const float* zb = z + (size_t)b * CHW + p0;  // element (c, n) at zb[c*HW + n]

    float rmin[4];
    int   ridx[4];
#pragma unroll
    for (int i = 0; i < 4; i++) { rmin[i] = 3.4e38f; ridx[i] = 0; }

    const u64 NEG2 = pack2(-2.f, -2.f);

    for (int k0 = 0; k0 < K_CODES; k0 += BK) {
        // acc2[i][j2] holds (acc[i][2*j2], acc[i][2*j2+1]) packed as f32x2
        u64 acc2[4][4];
#pragma unroll
        for (int i = 0; i < 4; i++)
#pragma unroll
            for (int j = 0; j < 4; j++) acc2[i][j] = 0ull;

        for (int c0 = 0; c0 < C_DIM; c0 += CC) {
            // load z tile: 32 x 64 floats = 512 float4 (2 per thread), coalesced
#pragma unroll
            for (int u = 0; u < 2; u++) {
                int idx = tid + u * 256;     // 0..511
                int c = idx >> 4;            // 16 float4 per row
                int n4 = idx & 15;
                *(float4*)&zs[c][n4 * 4] =
                    *(const float4*)&zb[(c0 + c) * HW + n4 * 4];
            }
            // load e tile: 32 x 128 floats = 1024 float4 (4 per thread), coalesced
#pragma unroll
            for (int u = 0; u < 4; u++) {
                int idx = tid + u * 256;     // 0..1023
                int c = idx >> 5;            // 32 float4 per row
                int k4 = idx & 31;
                *(float4*)&es[c][k4 * 4] =
                    *(const float4*)&g_embT[(c0 + c) * K_CODES + k0 + k4 * 4];
            }
            __syncthreads();

#pragma unroll
            for (int cc = 0; cc < CC; cc++) {
                float4 zf = *(float4*)&zs[cc][ty * 4];
                // e pairs straight out of the 128-bit shared loads
                ulonglong2 ea = *(ulonglong2*)&es[cc][tx * 4];
                ulonglong2 eb = *(ulonglong2*)&es[cc][tx * 4 + 64];
                u64 ee[4] = {ea.x, ea.y, eb.x, eb.y};
                u64 zz[4];
                zz[0] = pack2(zf.x, zf.x);
                zz[1] = pack2(zf.y, zf.y);
                zz[2] = pack2(zf.z, zf.z);
                zz[3] = pack2(zf.w, zf.w);
#pragma unroll
                for (int i = 0; i < 4; i++)
#pragma unroll
                    for (int j = 0; j < 4; j++)
                        ffma2_acc(acc2[i][j], zz[i], ee[j]);
            }
            __syncthreads();
        }

        // distances + running argmin. k ascending within thread sweep and '<'
        // keeps the lowest index on exact ties (argmin semantics).
        ulonglong2 enA = *(const ulonglong2*)&g_enorm[k0 + tx * 4];
        ulonglong2 enB = *(const ulonglong2*)&g_enorm[k0 + tx * 4 + 64];
        u64 en[4] = {enA.x, enA.y, enB.x, enB.y};
#pragma unroll
        for (int j2 = 0; j2 < 4; j2++) {
            int kbase = (j2 < 2) ? (k0 + tx * 4 + j2 * 2)
                                 : (k0 + tx * 4 + 64 + (j2 - 2) * 2);
#pragma unroll
            for (int i = 0; i < 4; i++) {
                u64 d2 = ffma2(acc2[i][j2], NEG2, en[j2]);  // en - 2*acc
                float dlo, dhi;
                unpack2(d2, dlo, dhi);
                if (dlo < rmin[i]) { rmin[i] = dlo; ridx[i] = kbase; }
                if (dhi < rmin[i]) { rmin[i] = dhi; ridx[i] = kbase + 1; }
            }
        }
    }

    // cross-thread reduction (16 col-groups share each row); tie -> lower idx
#pragma unroll
    for (int i = 0; i < 4; i++) {
        red_min[ty * 4 + i][tx] = rmin[i];
        red_idx[ty * 4 + i][tx] = ridx[i];
    }
    __syncthreads();
    if (tid < BN) {
        float m = red_min[tid][0];
        int mi  = red_idx[tid][0];
#pragma unroll
        for (int t = 1; t < 16; t++) {
            float v = red_min[tid][t];
            int vi  = red_idx[tid][t];
            if (v < m || (v == m && vi < mi)) { m = v; mi = vi; }
        }
        g_argmin[n0 + tid] = mi;
    }
}

// ---------------------------------------------------------------------------
// Gather: out[b,c,h,w] = emb[argmin[n]][c]
// ---------------------------------------------------------------------------
__global__ void gather_kernel(const float* __restrict__ emb,
                              float* __restrict__ out) {
    int t = blockIdx.x * blockDim.x + threadIdx.x;  // over N*C/4 float4s
    int p4 = t & 255;
    int c  = (t >> 8) & 255;
    int b  = t >> 16;
    int nb = b * HW + p4 * 4;
    float4 o;
    o.x = __ldg(&emb[g_argmin[nb + 0] * C_DIM + c]);
    o.y = __ldg(&emb[g_argmin[nb + 1] * C_DIM + c]);
    o.z = __ldg(&emb[g_argmin[nb + 2] * C_DIM + c]);
    o.w = __ldg(&emb[g_argmin[nb + 3] * C_DIM + c]);
    ((float4*)out)[t] = o;
}

extern "C" void kernel_launch(void* const* d_in, const int* in_sizes, int n_in,
                              void* d_out, int out_size) {
    (void)in_sizes; (void)n_in; (void)out_size;
    const float* z   = (const float*)d_in[0];
    const float* emb = (const float*)d_in[1];
    float* out = (float*)d_out;

    prep_transpose_kernel<<<dim3(K_CODES / 32, C_DIM / 32), dim3(32, 8)>>>(emb);
    enorm_kernel<<<K_CODES / 8, dim3(32, 8)>>>(emb);
    argmin_kernel<<<N_VEC / BN, 256>>>(z);
    gather_kernel<<<(N_VEC * C_DIM / 4) / 256, 256>>>(emb, out);
}

// round 4
// speedup vs baseline: 1.1663x; 1.1611x over previous
#include <cuda_runtime.h>
#include <cstdint>

#define C_DIM 256
#define K_CODES 8192
#define N_VEC 16384
#define HW 1024       // H*W
#define CHW 262144    // C*H*W

#define MT 128                 // rows per CTA
#define NT 128                 // codes per tile
#define KC 32                  // c per chunk
#define NTILES (K_CODES / NT)  // 64
#define NCHUNK (C_DIM / KC)    // 8

#define RS 36                  // padded smem row stride in words (bank-spread)
#define TW (128 * RS)          // words per tile buffer
#define SMEM_BYTES (2 * 4 * TW * 4)   // 2 stages x {Ahi,Alo,Bhi,Blo}

// ------------------------- device-global scratch ---------------------------
__device__ uint32_t g_z_hi[N_VEC * C_DIM];     // tf32 hi bits, [n][c]
__device__ uint32_t g_z_lo[N_VEC * C_DIM];     // tf32 lo bits
__device__ float    g_zT  [N_VEC * C_DIM];     // exact fp32, [n][c]
__device__ uint32_t g_e_hi[K_CODES * C_DIM];   // [k][c]
__device__ uint32_t g_e_lo[K_CODES * C_DIM];
__device__ float    g_enorm[K_CODES];
__device__ int      g_cand [N_VEC * 2];        // top-2 candidate codes per row
__device__ int      g_argmin[N_VEC];

// ------------------------------ helpers ------------------------------------
__device__ __forceinline__ uint32_t smem_u32(const void* p) {
    uint32_t a;
    asm("{ .reg .u64 t; cvta.to.shared.u64 t, %1; cvt.u32.u64 %0, t; }"
        : "=r"(a) : "l"(p));
    return a;
}
__device__ __forceinline__ uint32_t cvt_tf32(float v) {
    uint32_t r;
    asm("cvt.rna.tf32.f32 %0, %1;" : "=r"(r) : "f"(v));
    return r;
}
__device__ __forceinline__ void cpasync16(uint32_t s, const void* g) {
    asm volatile("cp.async.cg.shared.global [%0], [%1], 16;" :: "r"(s), "l"(g));
}
// D += A(tf32,row) * B(tf32,col), m16n8k8
__device__ __forceinline__ void mma_t(float* d, const uint32_t* a, const uint32_t* b) {
    asm("mma.sync.aligned.m16n8k8.row.col.f32.tf32.tf32.f32 "
        "{%0,%1,%2,%3}, {%4,%5,%6,%7}, {%8,%9}, {%0,%1,%2,%3};"
        : "+f"(d[0]), "+f"(d[1]), "+f"(d[2]), "+f"(d[3])
        : "r"(a[0]), "r"(a[1]), "r"(a[2]), "r"(a[3]), "r"(b[0]), "r"(b[1]));
}

// ------------------------------ prep kernels -------------------------------
__global__ void zprep_kernel(const float* __restrict__ z) {
    __shared__ float tile[32][33];
    int b  = blockIdx.z;
    int c0 = blockIdx.y * 32;
    int p0 = blockIdx.x * 32;
    int tx = threadIdx.x, ty = threadIdx.y;   // 32 x 8
#pragma unroll
    for (int j = 0; j < 4; j++)
        tile[ty + 8 * j][tx] = z[b * CHW + (c0 + ty + 8 * j) * HW + p0 + tx];
    __syncthreads();
#pragma unroll
    for (int j = 0; j < 4; j++) {
        float v = tile[tx][ty + 8 * j];
        uint32_t hi = cvt_tf32(v);
        uint32_t lo = cvt_tf32(v - __uint_as_float(hi));
        int n = b * HW + p0 + ty + 8 * j;
        g_zT  [n * C_DIM + c0 + tx] = v;
        g_z_hi[n * C_DIM + c0 + tx] = hi;
        g_z_lo[n * C_DIM + c0 + tx] = lo;
    }
}

__global__ void embprep_kernel(const float* __restrict__ emb) {
    int i = blockIdx.x * 256 + threadIdx.x;
    float v = emb[i];
    uint32_t hi = cvt_tf32(v);
    g_e_hi[i] = hi;
    g_e_lo[i] = cvt_tf32(v - __uint_as_float(hi));
}

__global__ void enorm_kernel(const float* __restrict__ emb) {
    int k = blockIdx.x * 8 + threadIdx.y;
    const float* row = emb + k * C_DIM;
    float s = 0.f;
    for (int c = threadIdx.x; c < C_DIM; c += 32) {
        float v = row[c];
        s += v * v;
    }
#pragma unroll
    for (int o = 16; o; o >>= 1) s += __shfl_xor_sync(0xffffffffu, s, o);
    if (threadIdx.x == 0) g_enorm[k] = s;
}

// ------------------------------ main kernel --------------------------------
__global__ __launch_bounds__(256, 1) void vq_mma_kernel() {
    extern __shared__ uint32_t sm[];
    int tid  = threadIdx.x;
    int lane = tid & 31, wid = tid >> 5;
    int mw = wid >> 2, nw = wid & 3;     // 2 M-warps x 4 N-warps
    int g = lane >> 2, t = lane & 3;
    int n0 = blockIdx.x * MT;

    const uint32_t* zh = g_z_hi + (size_t)n0 * C_DIM;
    const uint32_t* zl = g_z_lo + (size_t)n0 * C_DIM;

    // running top-2 per owned row slot (mf*2+h), strict order, k ascending
    float m1[8], m2[8];
    int   i1[8], i2[8];
#pragma unroll
    for (int r = 0; r < 8; r++) {
        m1[r] = 3.4e38f; m2[r] = 3.4e38f; i1[r] = 0; i2[r] = 0;
    }

    float acc[4][4][4];
#pragma unroll
    for (int a = 0; a < 4; a++)
#pragma unroll
        for (int b = 0; b < 4; b++)
#pragma unroll
            for (int c = 0; c < 4; c++) acc[a][b][c] = 0.f;

    for (int tt = 0; tt < NTILES; tt++) {
        int k0 = tt * NT;
        const uint32_t* eh = g_e_hi + (size_t)k0 * C_DIM;
        const uint32_t* el = g_e_lo + (size_t)k0 * C_DIM;

        // prologue: chunk 0 -> stage 0
        {
            uint32_t s0 = smem_u32(sm);
#pragma unroll
            for (int i = 0; i < 4; i++) {
                int idx = tid + i * 256;          // 0..1023
                int r = idx >> 3, q = idx & 7;
                uint32_t off = (uint32_t)(r * RS + q * 4) * 4;
                cpasync16(s0 + 0 * TW * 4 + off, zh + r * C_DIM + q * 4);
                cpasync16(s0 + 1 * TW * 4 + off, zl + r * C_DIM + q * 4);
                cpasync16(s0 + 2 * TW * 4 + off, eh + r * C_DIM + q * 4);
                cpasync16(s0 + 3 * TW * 4 + off, el + r * C_DIM + q * 4);
            }
            asm volatile("cp.async.commit_group;" ::: "memory");
        }

        for (int ch = 0; ch < NCHUNK; ch++) {
            int stage = ch & 1;
            if (ch < NCHUNK - 1) {
                int c0 = (ch + 1) * KC;
                int ns = (ch + 1) & 1;
                uint32_t s0 = smem_u32(sm) + (uint32_t)(ns * 4 * TW) * 4;
#pragma unroll
                for (int i = 0; i < 4; i++) {
                    int idx = tid + i * 256;
                    int r = idx >> 3, q = idx & 7;
                    uint32_t off = (uint32_t)(r * RS + q * 4) * 4;
                    cpasync16(s0 + 0 * TW * 4 + off, zh + r * C_DIM + c0 + q * 4);
                    cpasync16(s0 + 1 * TW * 4 + off, zl + r * C_DIM + c0 + q * 4);
                    cpasync16(s0 + 2 * TW * 4 + off, eh + r * C_DIM + c0 + q * 4);
                    cpasync16(s0 + 3 * TW * 4 + off, el + r * C_DIM + c0 + q * 4);
                }
                asm volatile("cp.async.commit_group;" ::: "memory");
                asm volatile("cp.async.wait_group 1;" ::: "memory");
            } else {
                asm volatile("cp.async.wait_group 0;" ::: "memory");
            }
            __syncthreads();

            const uint32_t* Ahi = sm + (stage * 4 + 0) * TW;
            const uint32_t* Alo = sm + (stage * 4 + 1) * TW;
            const uint32_t* Bhi = sm + (stage * 4 + 2) * TW;
            const uint32_t* Blo = sm + (stage * 4 + 3) * TW;

#pragma unroll
            for (int ks = 0; ks < 4; ks++) {
                int kk = ks * 8;
                uint32_t bh[4][2], bl[4][2];
#pragma unroll
                for (int nf = 0; nf < 4; nf++) {
                    int br = nw * 32 + nf * 8 + g;
                    bh[nf][0] = Bhi[br * RS + kk + t];
                    bh[nf][1] = Bhi[br * RS + kk + t + 4];
                    bl[nf][0] = Blo[br * RS + kk + t];
                    bl[nf][1] = Blo[br * RS + kk + t + 4];
                }
#pragma unroll
                for (int mf = 0; mf < 4; mf++) {
                    int r0 = mw * 64 + mf * 16 + g, r1 = r0 + 8;
                    uint32_t ah[4] = {Ahi[r0 * RS + kk + t], Ahi[r1 * RS + kk + t],
                                      Ahi[r0 * RS + kk + t + 4], Ahi[r1 * RS + kk + t + 4]};
                    uint32_t al[4] = {Alo[r0 * RS + kk + t], Alo[r1 * RS + kk + t],
                                      Alo[r0 * RS + kk + t + 4], Alo[r1 * RS + kk + t + 4]};
#pragma unroll
                    for (int nf = 0; nf < 4; nf++) {
                        mma_t(acc[mf][nf], ah, bh[nf]);
                        mma_t(acc[mf][nf], ah, bl[nf]);
                        mma_t(acc[mf][nf], al, bh[nf]);
                    }
                }
            }
            __syncthreads();
        }

        // epilogue: d = ||e||^2 - 2*dot ; update per-row top-2 (k ascending)
#pragma unroll
        for (int nf = 0; nf < 4; nf++) {
            int kb = k0 + nw * 32 + nf * 8 + 2 * t;
            float e0 = __ldg(&g_enorm[kb]);
            float e1 = __ldg(&g_enorm[kb + 1]);
#pragma unroll
            for (int mf = 0; mf < 4; mf++) {
#pragma unroll
                for (int h = 0; h < 2; h++) {
                    int rr = mf * 2 + h;
                    float d0 = fmaf(-2.f, acc[mf][nf][h * 2 + 0], e0);
                    float d1 = fmaf(-2.f, acc[mf][nf][h * 2 + 1], e1);
                    if (d0 < m1[rr]) { m2[rr] = m1[rr]; i2[rr] = i1[rr]; m1[rr] = d0; i1[rr] = kb; }
                    else if (d0 < m2[rr]) { m2[rr] = d0; i2[rr] = kb; }
                    if (d1 < m1[rr]) { m2[rr] = m1[rr]; i2[rr] = i1[rr]; m1[rr] = d1; i1[rr] = kb + 1; }
                    else if (d1 < m2[rr]) { m2[rr] = d1; i2[rr] = kb + 1; }
                    acc[mf][nf][h * 2 + 0] = 0.f;
                    acc[mf][nf][h * 2 + 1] = 0.f;
                }
            }
        }
    }

    // merge top-2 across the 4 lanes sharing each row (disjoint code sets)
#pragma unroll
    for (int rr = 0; rr < 8; rr++) {
#pragma unroll
        for (int dd = 1; dd <= 2; dd <<= 1) {
            float n1 = __shfl_xor_sync(0xffffffffu, m1[rr], dd);
            int   j1 = __shfl_xor_sync(0xffffffffu, i1[rr], dd);
            float n2 = __shfl_xor_sync(0xffffffffu, m2[rr], dd);
            int   j2 = __shfl_xor_sync(0xffffffffu, i2[rr], dd);
            if (n1 < m1[rr] || (n1 == m1[rr] && j1 < i1[rr])) {
                m2[rr] = m1[rr]; i2[rr] = i1[rr]; m1[rr] = n1; i1[rr] = j1;
            } else if (n1 < m2[rr] || (n1 == m2[rr] && j1 < i2[rr])) {
                m2[rr] = n1; i2[rr] = j1;
            }
            if (n2 < m2[rr] || (n2 == m2[rr] && j2 < i2[rr])) { m2[rr] = n2; i2[rr] = j2; }
        }
    }

    __syncthreads();
    float4* red = (float4*)sm;   // [128 rows][4 n-warps]
    if (t == 0) {
#pragma unroll
        for (int rr = 0; rr < 8; rr++) {
            int row = mw * 64 + (rr >> 1) * 16 + g + 8 * (rr & 1);
            red[row * 4 + nw] = make_float4(m1[rr], __int_as_float(i1[rr]),
                                            m2[rr], __int_as_float(i2[rr]));
        }
    }
    __syncthreads();
    if (tid < MT) {
        float4 v = red[tid * 4 + 0];
        float a1 = v.x; int b1 = __float_as_int(v.y);
        float a2 = v.z; int b2 = __float_as_int(v.w);
#pragma unroll
        for (int w = 1; w < 4; w++) {
            float4 u = red[tid * 4 + w];
            float n1 = u.x; int j1 = __float_as_int(u.y);
            float n2 = u.z; int j2 = __float_as_int(u.w);
            if (n1 < a1 || (n1 == a1 && j1 < b1)) { a2 = a1; b2 = b1; a1 = n1; b1 = j1; }
            else if (n1 < a2 || (n1 == a2 && j1 < b2)) { a2 = n1; b2 = j1; }
            if (n2 < a2 || (n2 == a2 && j2 < b2)) { a2 = n2; b2 = j2; }
        }
        g_cand[(n0 + tid) * 2 + 0] = b1;
        g_cand[(n0 + tid) * 2 + 1] = b2;
    }
}

// ---------------------- exact fp32 rescore of top-2 ------------------------
__global__ void rescore_kernel(const float* __restrict__ emb) {
    int wid = threadIdx.x >> 5, lane = threadIdx.x & 31;
    int n = blockIdx.x * 8 + wid;
    int c1 = g_cand[n * 2], c2 = g_cand[n * 2 + 1];
    const float* zr = g_zT + (size_t)n * C_DIM;
    const float* e1 = emb + (size_t)c1 * C_DIM;
    const float* e2 = emb + (size_t)c2 * C_DIM;
    float s1 = 0.f, s2 = 0.f;
#pragma unroll
    for (int c = lane; c < C_DIM; c += 32) {
        float zv = zr[c];
        float d1 = zv - e1[c], d2 = zv - e2[c];
        s1 += d1 * d1; s2 += d2 * d2;
    }
#pragma unroll
    for (int o = 16; o; o >>= 1) {
        s1 += __shfl_xor_sync(0xffffffffu, s1, o);
        s2 += __shfl_xor_sync(0xffffffffu, s2, o);
    }
    if (lane == 0)
        g_argmin[n] = (s1 < s2 || (s1 == s2 && c1 < c2)) ? c1 : c2;
}

// ------------------------------ gather -------------------------------------
__global__ void gather_kernel(const float* __restrict__ emb,
                              float* __restrict__ out) {
    int t = blockIdx.x * blockDim.x + threadIdx.x;
    int p4 = t & 255;
    int c  = (t >> 8) & 255;
    int b  = t >> 16;
    int nb = b * HW + p4 * 4;
    float4 o;
    o.x = __ldg(&emb[g_argmin[nb + 0] * C_DIM + c]);
    o.y = __ldg(&emb[g_argmin[nb + 1] * C_DIM + c]);
    o.z = __ldg(&emb[g_argmin[nb + 2] * C_DIM + c]);
    o.w = __ldg(&emb[g_argmin[nb + 3] * C_DIM + c]);
    ((float4*)out)[t] = o;
}

// ------------------------------ launch --------------------------------------
extern "C" void kernel_launch(void* const* d_in, const int* in_sizes, int n_in,
                              void* d_out, int out_size) {
    (void)in_sizes; (void)n_in; (void)out_size;
    const float* z   = (const float*)d_in[0];
    const float* emb = (const float*)d_in[1];
    float* out = (float*)d_out;

    static int smem_set = 0;
    if (!smem_set) {
        cudaFuncSetAttribute(vq_mma_kernel,
                             cudaFuncAttributeMaxDynamicSharedMemorySize, SMEM_BYTES);
        smem_set = 1;
    }

    zprep_kernel<<<dim3(HW / 32, C_DIM / 32, 16), dim3(32, 8)>>>(z);
    embprep_kernel<<<(K_CODES * C_DIM) / 256, 256>>>(emb);
    enorm_kernel<<<K_CODES / 8, dim3(32, 8)>>>(emb);
    vq_mma_kernel<<<N_VEC / MT, 256, SMEM_BYTES>>>();
    rescore_kernel<<<N_VEC / 8, 256>>>(emb);
    gather_kernel<<<(N_VEC * C_DIM / 4) / 256, 256>>>(emb, out);
}

// round 9
// speedup vs baseline: 1.1950x; 1.0246x over previous
#include <cuda_runtime.h>
#include <cstdint>

#define C_DIM 256
#define K_CODES 8192
#define N_VEC 16384
#define HW 1024       // H*W
#define CHW 262144    // C*H*W

#define MT 64                  // rows per CTA
#define NT 128                 // codes per tile
#define KC 32                  // c per chunk
#define NTILES (K_CODES / NT)  // 64
#define NCHUNK (C_DIM / KC)    // 8

#define RS 36                  // padded smem row stride in words
// per-stage words: Ahi(64*36) Alo(64*36) Bhi(128*36) Blo(128*36)
#define AHI_W 0
#define ALO_W (64 * RS)
#define BHI_W (128 * RS)
#define BLO_W (256 * RS)
#define STAGE_W (384 * RS)     // 13824 words
#define SMEM_BYTES (2 * STAGE_W * 4)   // 110592 B

// ------------------------- device-global scratch ---------------------------
__device__ uint32_t g_z_hi[N_VEC * C_DIM];     // tf32 hi bits, [n][c]
__device__ uint32_t g_z_lo[N_VEC * C_DIM];     // tf32 lo bits
__device__ float    g_zT  [N_VEC * C_DIM];     // exact fp32, [n][c]
__device__ uint32_t g_e_hi[K_CODES * C_DIM];   // [k][c]
__device__ uint32_t g_e_lo[K_CODES * C_DIM];
__device__ float    g_enorm[K_CODES];
__device__ int      g_cand [N_VEC * 2];        // top-2 candidate codes per row
__device__ int      g_argmin[N_VEC];

// ------------------------------ helpers ------------------------------------
__device__ __forceinline__ uint32_t smem_u32(const void* p) {
    uint32_t a;
    asm("{ .reg .u64 t; cvta.to.shared.u64 t, %1; cvt.u32.u64 %0, t; }"
        : "=r"(a) : "l"(p));
    return a;
}
__device__ __forceinline__ uint32_t cvt_tf32(float v) {
    uint32_t r;
    asm("cvt.rna.tf32.f32 %0, %1;" : "=r"(r) : "f"(v));
    return r;
}
__device__ __forceinline__ void cpasync16(uint32_t s, const void* g) {
    asm volatile("cp.async.cg.shared.global [%0], [%1], 16;" :: "r"(s), "l"(g));
}
// D += A(tf32,row) * B(tf32,col), m16n8k8
__device__ __forceinline__ void mma_t(float* d, const uint32_t* a, const uint32_t* b) {
    asm("mma.sync.aligned.m16n8k8.row.col.f32.tf32.tf32.f32 "
        "{%0,%1,%2,%3}, {%4,%5,%6,%7}, {%8,%9}, {%0,%1,%2,%3};"
        : "+f"(d[0]), "+f"(d[1]), "+f"(d[2]), "+f"(d[3])
        : "r"(a[0]), "r"(a[1]), "r"(a[2]), "r"(a[3]), "r"(b[0]), "r"(b[1]));
}

// ------------------------------ prep kernels -------------------------------
__global__ void zprep_kernel(const float* __restrict__ z) {
    __shared__ float tile[32][33];
    int b  = blockIdx.z;
    int c0 = blockIdx.y * 32;
    int p0 = blockIdx.x * 32;
    int tx = threadIdx.x, ty = threadIdx.y;   // 32 x 8
#pragma unroll
    for (int j = 0; j < 4; j++)
        tile[ty + 8 * j][tx] = z[b * CHW + (c0 + ty + 8 * j) * HW + p0 + tx];
    __syncthreads();
#pragma unroll
    for (int j = 0; j < 4; j++) {
        float v = tile[tx][ty + 8 * j];
        uint32_t hi = cvt_tf32(v);
        uint32_t lo = cvt_tf32(v - __uint_as_float(hi));
        int n = b * HW + p0 + ty + 8 * j;
        g_zT  [n * C_DIM + c0 + tx] = v;
        g_z_hi[n * C_DIM + c0 + tx] = hi;
        g_z_lo[n * C_DIM + c0 + tx] = lo;
    }
}

__global__ void embprep_kernel(const float* __restrict__ emb) {
    int i = blockIdx.x * 256 + threadIdx.x;
    float v = emb[i];
    uint32_t hi = cvt_tf32(v);
    g_e_hi[i] = hi;
    g_e_lo[i] = cvt_tf32(v - __uint_as_float(hi));
}

__global__ void enorm_kernel(const float* __restrict__ emb) {
    int k = blockIdx.x * 8 + threadIdx.y;
    const float* row = emb + k * C_DIM;
    float s = 0.f;
    for (int c = threadIdx.x; c < C_DIM; c += 32) {
        float v = row[c];
        s += v * v;
    }
#pragma unroll
    for (int o = 16; o; o >>= 1) s += __shfl_xor_sync(0xffffffffu, s, o);
    if (threadIdx.x == 0) g_enorm[k] = s;
}

// ------------------------------ main kernel --------------------------------
// 128 threads = 4 N-warps; each warp: mf=4 (all 64 rows), nf=4 (32 codes).
// 2 CTAs / SM for latency hiding across sync boundaries.
__global__ __launch_bounds__(128, 2) void vq_mma_kernel() {
    extern __shared__ uint32_t sm[];
    int tid  = threadIdx.x;
    int lane = tid & 31, nw = tid >> 5;   // warp = N-warp
    int g = lane >> 2, t = lane & 3;
    int n0 = blockIdx.x * MT;

    const uint32_t* zh = g_z_hi + (size_t)n0 * C_DIM;
    const uint32_t* zl = g_z_lo + (size_t)n0 * C_DIM;

    // running top-2 per owned row slot (mf*2+h), k ascending
    float m1[8], m2[8];
    int   i1[8], i2[8];
#pragma unroll
    for (int r = 0; r < 8; r++) {
        m1[r] = 3.4e38f; m2[r] = 3.4e38f; i1[r] = 0; i2[r] = 0;
    }

    float acc[4][4][4];
#pragma unroll
    for (int a = 0; a < 4; a++)
#pragma unroll
        for (int b = 0; b < 4; b++)
#pragma unroll
            for (int c = 0; c < 4; c++) acc[a][b][c] = 0.f;

    for (int tt = 0; tt < NTILES; tt++) {
        int k0 = tt * NT;
        const uint32_t* eh = g_e_hi + (size_t)k0 * C_DIM;
        const uint32_t* el = g_e_lo + (size_t)k0 * C_DIM;

        // prologue: chunk 0 -> stage 0
        {
            uint32_t s0 = smem_u32(sm);
#pragma unroll
            for (int i = 0; i < 4; i++) {        // A: 512 f4
                int idx = tid + i * 128;
                int r = idx >> 3, q = idx & 7;
                uint32_t off = (uint32_t)(r * RS + q * 4) * 4;
                cpasync16(s0 + AHI_W * 4 + off, zh + r * C_DIM + q * 4);
                cpasync16(s0 + ALO_W * 4 + off, zl + r * C_DIM + q * 4);
            }
#pragma unroll
            for (int i = 0; i < 8; i++) {        // B: 1024 f4
                int idx = tid + i * 128;
                int r = idx >> 3, q = idx & 7;
                uint32_t off = (uint32_t)(r * RS + q * 4) * 4;
                cpasync16(s0 + BHI_W * 4 + off, eh + r * C_DIM + q * 4);
                cpasync16(s0 + BLO_W * 4 + off, el + r * C_DIM + q * 4);
            }
            asm volatile("cp.async.commit_group;" ::: "memory");
        }

        for (int ch = 0; ch < NCHUNK; ch++) {
            int stage = ch & 1;
            if (ch < NCHUNK - 1) {
                int c0 = (ch + 1) * KC;
                uint32_t s0 = smem_u32(sm) + (uint32_t)(((ch + 1) & 1) * STAGE_W) * 4;
#pragma unroll
                for (int i = 0; i < 4; i++) {
                    int idx = tid + i * 128;
                    int r = idx >> 3, q = idx & 7;
                    uint32_t off = (uint32_t)(r * RS + q * 4) * 4;
                    cpasync16(s0 + AHI_W * 4 + off, zh + r * C_DIM + c0 + q * 4);
                    cpasync16(s0 + ALO_W * 4 + off, zl + r * C_DIM + c0 + q * 4);
                }
#pragma unroll
                for (int i = 0; i < 8; i++) {
                    int idx = tid + i * 128;
                    int r = idx >> 3, q = idx & 7;
                    uint32_t off = (uint32_t)(r * RS + q * 4) * 4;
                    cpasync16(s0 + BHI_W * 4 + off, eh + r * C_DIM + c0 + q * 4);
                    cpasync16(s0 + BLO_W * 4 + off, el + r * C_DIM + c0 + q * 4);
                }
                asm volatile("cp.async.commit_group;" ::: "memory");
                asm volatile("cp.async.wait_group 1;" ::: "memory");
            } else {
                asm volatile("cp.async.wait_group 0;" ::: "memory");
            }
            __syncthreads();

            const uint32_t* Ahi = sm + stage * STAGE_W + AHI_W;
            const uint32_t* Alo = sm + stage * STAGE_W + ALO_W;
            const uint32_t* Bhi = sm + stage * STAGE_W + BHI_W;
            const uint32_t* Blo = sm + stage * STAGE_W + BLO_W;

#pragma unroll
            for (int ks = 0; ks < 4; ks++) {
                int kk = ks * 8;
                uint32_t bh[4][2], bl[4][2];
#pragma unroll
                for (int nf = 0; nf < 4; nf++) {
                    int br = nw * 32 + nf * 8 + g;
                    bh[nf][0] = Bhi[br * RS + kk + t];
                    bh[nf][1] = Bhi[br * RS + kk + t + 4];
                    bl[nf][0] = Blo[br * RS + kk + t];
                    bl[nf][1] = Blo[br * RS + kk + t + 4];
                }
#pragma unroll
                for (int mf = 0; mf < 4; mf++) {
                    int r0 = mf * 16 + g, r1 = r0 + 8;
                    uint32_t ah[4] = {Ahi[r0 * RS + kk + t], Ahi[r1 * RS + kk + t],
                                      Ahi[r0 * RS + kk + t + 4], Ahi[r1 * RS + kk + t + 4]};
                    uint32_t al[4] = {Alo[r0 * RS + kk + t], Alo[r1 * RS + kk + t],
                                      Alo[r0 * RS + kk + t + 4], Alo[r1 * RS + kk + t + 4]};
#pragma unroll
                    for (int nf = 0; nf < 4; nf++) {
                        mma_t(acc[mf][nf], ah, bh[nf]);
                        mma_t(acc[mf][nf], ah, bl[nf]);
                        mma_t(acc[mf][nf], al, bh[nf]);
                    }
                }
            }
            __syncthreads();
        }

        // epilogue: d = ||e||^2 - 2*dot ; per-row top-2 (k ascending)
#pragma unroll
        for (int nf = 0; nf < 4; nf++) {
            int kb = k0 + nw * 32 + nf * 8 + 2 * t;
            float e0 = __ldg(&g_enorm[kb]);
            float e1 = __ldg(&g_enorm[kb + 1]);
#pragma unroll
            for (int mf = 0; mf < 4; mf++) {
#pragma unroll
                for (int h = 0; h < 2; h++) {
                    int rr = mf * 2 + h;
                    float d0 = fmaf(-2.f, acc[mf][nf][h * 2 + 0], e0);
                    float d1 = fmaf(-2.f, acc[mf][nf][h * 2 + 1], e1);
                    if (d0 < m1[rr]) { m2[rr] = m1[rr]; i2[rr] = i1[rr]; m1[rr] = d0; i1[rr] = kb; }
                    else if (d0 < m2[rr]) { m2[rr] = d0; i2[rr] = kb; }
                    if (d1 < m1[rr]) { m2[rr] = m1[rr]; i2[rr] = i1[rr]; m1[rr] = d1; i1[rr] = kb + 1; }
                    else if (d1 < m2[rr]) { m2[rr] = d1; i2[rr] = kb + 1; }
                    acc[mf][nf][h * 2 + 0] = 0.f;
                    acc[mf][nf][h * 2 + 1] = 0.f;
                }
            }
        }
    }

    // merge top-2 across the 4 lanes sharing each row (disjoint code sets)
#pragma unroll
    for (int rr = 0; rr < 8; rr++) {
#pragma unroll
        for (int dd = 1; dd <= 2; dd <<= 1) {
            float n1 = __shfl_xor_sync(0xffffffffu, m1[rr], dd);
            int   j1 = __shfl_xor_sync(0xffffffffu, i1[rr], dd);
            float n2 = __shfl_xor_sync(0xffffffffu, m2[rr], dd);
            int   j2 = __shfl_xor_sync(0xffffffffu, i2[rr], dd);
            if (n1 < m1[rr] || (n1 == m1[rr] && j1 < i1[rr])) {
                m2[rr] = m1[rr]; i2[rr] = i1[rr]; m1[rr] = n1; i1[rr] = j1;
            } else if (n1 < m2[rr] || (n1 == m2[rr] && j1 < i2[rr])) {
                m2[rr] = n1; i2[rr] = j1;
            }
            if (n2 < m2[rr] || (n2 == m2[rr] && j2 < i2[rr])) { m2[rr] = n2; i2[rr] = j2; }
        }
    }

    __syncthreads();
    float4* red = (float4*)sm;   // [64 rows][4 n-warps]
    if (t == 0) {
#pragma unroll
        for (int rr = 0; rr < 8; rr++) {
            int row = (rr >> 1) * 16 + g + 8 * (rr & 1);
            red[row * 4 + nw] = make_float4(m1[rr], __int_as_float(i1[rr]),
                                            m2[rr], __int_as_float(i2[rr]));
        }
    }
    __syncthreads();
    if (tid < MT) {
        float4 v = red[tid * 4 + 0];
        float a1 = v.x; int b1 = __float_as_int(v.y);
        float a2 = v.z; int b2 = __float_as_int(v.w);
#pragma unroll
        for (int w = 1; w < 4; w++) {
            float4 u = red[tid * 4 + w];
            float n1 = u.x; int j1 = __float_as_int(u.y);
            float n2 = u.z; int j2 = __float_as_int(u.w);
            if (n1 < a1 || (n1 == a1 && j1 < b1)) { a2 = a1; b2 = b1; a1 = n1; b1 = j1; }
            else if (n1 < a2 || (n1 == a2 && j1 < b2)) { a2 = n1; b2 = j1; }
            if (n2 < a2 || (n2 == a2 && j2 < b2)) { a2 = n2; b2 = j2; }
        }
        g_cand[(n0 + tid) * 2 + 0] = b1;
        g_cand[(n0 + tid) * 2 + 1] = b2;
    }
}

// ---------------------- exact fp32 rescore of top-2 ------------------------
__global__ void rescore_kernel(const float* __restrict__ emb) {
    int wid = threadIdx.x >> 5, lane = threadIdx.x & 31;
    int n = blockIdx.x * 8 + wid;
    int c1 = g_cand[n * 2], c2 = g_cand[n * 2 + 1];
    const float* zr = g_zT + (size_t)n * C_DIM;
    const float* e1 = emb + (size_t)c1 * C_DIM;
    const float* e2 = emb + (size_t)c2 * C_DIM;
    float s1 = 0.f, s2 = 0.f;
#pragma unroll
    for (int c = lane; c < C_DIM; c += 32) {
        float zv = zr[c];
        float d1 = zv - e1[c], d2 = zv - e2[c];
        s1 += d1 * d1; s2 += d2 * d2;
    }
#pragma unroll
    for (int o = 16; o; o >>= 1) {
        s1 += __shfl_xor_sync(0xffffffffu, s1, o);
        s2 += __shfl_xor_sync(0xffffffffu, s2, o);
    }
    if (lane == 0)
        g_argmin[n] = (s1 < s2 || (s1 == s2 && c1 < c2)) ? c1 : c2;
}

// ------------------------------ gather -------------------------------------
__global__ void gather_kernel(const float* __restrict__ emb,
                              float* __restrict__ out) {
    int t = blockIdx.x * blockDim.x + threadIdx.x;
    int p4 = t & 255;
    int c  = (t >> 8) & 255;
    int b  = t >> 16;
    int nb = b * HW + p4 * 4;
    float4 o;
    o.x = __ldg(&emb[g_argmin[nb + 0] * C_DIM + c]);
    o.y = __ldg(&emb[g_argmin[nb + 1] * C_DIM + c]);
    o.z = __ldg(&emb[g_argmin[nb + 2] * C_DIM + c]);
    o.w = __ldg(&emb[g_argmin[nb + 3] * C_DIM + c]);
    ((float4*)out)[t] = o;
}

// ------------------------------ launch --------------------------------------
extern "C" void kernel_launch(void* const* d_in, const int* in_sizes, int n_in,
                              void* d_out, int out_size) {
    (void)in_sizes; (void)n_in; (void)out_size;
    const float* z   = (const float*)d_in[0];
    const float* emb = (const float*)d_in[1];
    float* out = (float*)d_out;

    cudaFuncSetAttribute(vq_mma_kernel,
                         cudaFuncAttributeMaxDynamicSharedMemorySize, SMEM_BYTES);

    zprep_kernel<<<dim3(HW / 32, C_DIM / 32, 16), dim3(32, 8)>>>(z);
    embprep_kernel<<<(K_CODES * C_DIM) / 256, 256>>>(emb);
    enorm_kernel<<<K_CODES / 8, dim3(32, 8)>>>(emb);
    vq_mma_kernel<<<N_VEC / MT, 128, SMEM_BYTES>>>();
    rescore_kernel<<<N_VEC / 8, 256>>>(emb);
    gather_kernel<<<(N_VEC * C_DIM / 4) / 256, 256>>>(emb, out);
}

// round 10
// speedup vs baseline: 1.9076x; 1.5963x over previous
#include <cuda_runtime.h>
#include <cuda_bf16.h>
#include <cstdint>

#define C_DIM 256
#define K_CODES 8192
#define N_VEC 16384
#define HW 1024       // H*W
#define CHW 262144    // C*H*W

#define MT 64                  // rows per CTA
#define NT 128                 // codes per tile
#define KC 32                  // c per chunk
#define NTILES (K_CODES / NT)  // 64
#define NCHUNK (C_DIM / KC)    // 8

// smem: words are uint32 = bf16x2 pairs along c. 16 data words/row + 4 pad.
#define RS 20
#define AH_W 0
#define AM_W (64 * RS)
#define BH_W (128 * RS)
#define BM_W (256 * RS)
#define STAGE_W (384 * RS)               // 7680 words = 30720 B
#define SMEM_BYTES (2 * STAGE_W * 4)     // 61440 B

// ------------------------- device-global scratch ---------------------------
__device__ __nv_bfloat16 g_z_h[N_VEC * C_DIM];    // bf16 hi, [n][c]
__device__ __nv_bfloat16 g_z_m[N_VEC * C_DIM];    // bf16 mid
__device__ float         g_zT [N_VEC * C_DIM];    // exact fp32, [n][c]
__device__ __nv_bfloat16 g_e_h[K_CODES * C_DIM];  // [k][c]
__device__ __nv_bfloat16 g_e_m[K_CODES * C_DIM];
__device__ float         g_enorm[K_CODES];
__device__ int           g_cand [N_VEC * 2];      // top-2 candidates per row
__device__ int           g_argmin[N_VEC];

// ------------------------------ helpers ------------------------------------
__device__ __forceinline__ uint32_t smem_u32(const void* p) {
    uint32_t a;
    asm("{ .reg .u64 t; cvta.to.shared.u64 t, %1; cvt.u32.u64 %0, t; }"
        : "=r"(a) : "l"(p));
    return a;
}
__device__ __forceinline__ void cpasync16(uint32_t s, const void* g) {
    asm volatile("cp.async.cg.shared.global [%0], [%1], 16;" :: "r"(s), "l"(g));
}
// D += A(bf16,row) * B(bf16,col), m16n8k16
__device__ __forceinline__ void mma_bf(float* d, const uint32_t* a, const uint32_t* b) {
    asm("mma.sync.aligned.m16n8k16.row.col.f32.bf16.bf16.f32 "
        "{%0,%1,%2,%3}, {%4,%5,%6,%7}, {%8,%9}, {%0,%1,%2,%3};"
        : "+f"(d[0]), "+f"(d[1]), "+f"(d[2]), "+f"(d[3])
        : "r"(a[0]), "r"(a[1]), "r"(a[2]), "r"(a[3]), "r"(b[0]), "r"(b[1]));
}

// ------------------------------ prep kernels -------------------------------
__global__ void zprep_kernel(const float* __restrict__ z) {
    __shared__ float tile[32][33];
    int b  = blockIdx.z;
    int c0 = blockIdx.y * 32;
    int p0 = blockIdx.x * 32;
    int tx = threadIdx.x, ty = threadIdx.y;   // 32 x 8
#pragma unroll
    for (int j = 0; j < 4; j++)
        tile[ty + 8 * j][tx] = z[b * CHW + (c0 + ty + 8 * j) * HW + p0 + tx];
    __syncthreads();
#pragma unroll
    for (int j = 0; j < 4; j++) {
        float v = tile[tx][ty + 8 * j];
        __nv_bfloat16 h = __float2bfloat16(v);
        __nv_bfloat16 m = __float2bfloat16(v - __bfloat162float(h));
        int n = b * HW + p0 + ty + 8 * j;
        g_zT [n * C_DIM + c0 + tx] = v;
        g_z_h[n * C_DIM + c0 + tx] = h;
        g_z_m[n * C_DIM + c0 + tx] = m;
    }
}

__global__ void embprep_kernel(const float* __restrict__ emb) {
    int i = blockIdx.x * 256 + threadIdx.x;
    float v = emb[i];
    __nv_bfloat16 h = __float2bfloat16(v);
    g_e_h[i] = h;
    g_e_m[i] = __float2bfloat16(v - __bfloat162float(h));
}

__global__ void enorm_kernel(const float* __restrict__ emb) {
    int k = blockIdx.x * 8 + threadIdx.y;
    const float* row = emb + k * C_DIM;
    float s = 0.f;
    for (int c = threadIdx.x; c < C_DIM; c += 32) {
        float v = row[c];
        s += v * v;
    }
#pragma unroll
    for (int o = 16; o; o >>= 1) s += __shfl_xor_sync(0xffffffffu, s, o);
    if (threadIdx.x == 0) g_enorm[k] = s;
}

// ------------------------------ main kernel --------------------------------
// 128 threads = 4 N-warps; each warp: mf=4 (all 64 rows), nf=4 (32 codes).
// bf16x3 emulation: dot = hi*hi + hi*mid + mid*hi, fp32 accum; 3 term passes
// so each accumulator's MMAs are 16 apart (no RAW chains).
__global__ __launch_bounds__(128, 2) void vq_mma_kernel() {
    extern __shared__ uint32_t sm[];
    int tid  = threadIdx.x;
    int lane = tid & 31, nw = tid >> 5;
    int g = lane >> 2, t = lane & 3;
    int n0 = blockIdx.x * MT;

    const __nv_bfloat16* zh = g_z_h + (size_t)n0 * C_DIM;
    const __nv_bfloat16* zm = g_z_m + (size_t)n0 * C_DIM;

    float m1[8], m2[8];
    int   i1[8], i2[8];
#pragma unroll
    for (int r = 0; r < 8; r++) {
        m1[r] = 3.4e38f; m2[r] = 3.4e38f; i1[r] = 0; i2[r] = 0;
    }

    float acc[4][4][4];
#pragma unroll
    for (int a = 0; a < 4; a++)
#pragma unroll
        for (int b = 0; b < 4; b++)
#pragma unroll
            for (int c = 0; c < 4; c++) acc[a][b][c] = 0.f;

    for (int tt = 0; tt < NTILES; tt++) {
        int k0 = tt * NT;
        const __nv_bfloat16* eh = g_e_h + (size_t)k0 * C_DIM;
        const __nv_bfloat16* em = g_e_m + (size_t)k0 * C_DIM;

        // prologue: chunk 0 -> stage 0
        {
            uint32_t s0 = smem_u32(sm);
#pragma unroll
            for (int i = 0; i < 2; i++) {        // A: 256 x 16B per array
                int idx = tid + i * 128;
                int r = idx >> 2, q = idx & 3;
                uint32_t off = (uint32_t)(r * RS + q * 4) * 4;
                cpasync16(s0 + AH_W * 4 + off, zh + r * C_DIM + q * 8);
                cpasync16(s0 + AM_W * 4 + off, zm + r * C_DIM + q * 8);
            }
#pragma unroll
            for (int i = 0; i < 4; i++) {        // B: 512 x 16B per array
                int idx = tid + i * 128;
                int r = idx >> 2, q = idx & 3;
                uint32_t off = (uint32_t)(r * RS + q * 4) * 4;
                cpasync16(s0 + BH_W * 4 + off, eh + r * C_DIM + q * 8);
                cpasync16(s0 + BM_W * 4 + off, em + r * C_DIM + q * 8);
            }
            asm volatile("cp.async.commit_group;" ::: "memory");
        }

        for (int ch = 0; ch < NCHUNK; ch++) {
            int stage = ch & 1;
            if (ch < NCHUNK - 1) {
                int c0 = (ch + 1) * KC;
                uint32_t s0 = smem_u32(sm) + (uint32_t)(((ch + 1) & 1) * STAGE_W) * 4;
#pragma unroll
                for (int i = 0; i < 2; i++) {
                    int idx = tid + i * 128;
                    int r = idx >> 2, q = idx & 3;
                    uint32_t off = (uint32_t)(r * RS + q * 4) * 4;
                    cpasync16(s0 + AH_W * 4 + off, zh + r * C_DIM + c0 + q * 8);
                    cpasync16(s0 + AM_W * 4 + off, zm + r * C_DIM + c0 + q * 8);
                }
#pragma unroll
                for (int i = 0; i < 4; i++) {
                    int idx = tid + i * 128;
                    int r = idx >> 2, q = idx & 3;
                    uint32_t off = (uint32_t)(r * RS + q * 4) * 4;
                    cpasync16(s0 + BH_W * 4 + off, eh + r * C_DIM + c0 + q * 8);
                    cpasync16(s0 + BM_W * 4 + off, em + r * C_DIM + c0 + q * 8);
                }
                asm volatile("cp.async.commit_group;" ::: "memory");
                asm volatile("cp.async.wait_group 1;" ::: "memory");
            } else {
                asm volatile("cp.async.wait_group 0;" ::: "memory");
            }
            __syncthreads();

            const uint32_t* Ah = sm + stage * STAGE_W + AH_W;
            const uint32_t* Am = sm + stage * STAGE_W + AM_W;
            const uint32_t* Bh = sm + stage * STAGE_W + BH_W;
            const uint32_t* Bm = sm + stage * STAGE_W + BM_W;

#pragma unroll
            for (int ks = 0; ks < 2; ks++) {     // two k16 steps per KC=32
                int kk = ks * 8;                 // word offset
                uint32_t bh[4][2], bm[4][2];
#pragma unroll
                for (int nf = 0; nf < 4; nf++) {
                    int br = nw * 32 + nf * 8 + g;
                    bh[nf][0] = Bh[br * RS + kk + t];
                    bh[nf][1] = Bh[br * RS + kk + t + 4];
                    bm[nf][0] = Bm[br * RS + kk + t];
                    bm[nf][1] = Bm[br * RS + kk + t + 4];
                }
                uint32_t ah[4][4], am[4][4];
#pragma unroll
                for (int mf = 0; mf < 4; mf++) {
                    int r0 = mf * 16 + g, r1 = r0 + 8;
                    ah[mf][0] = Ah[r0 * RS + kk + t];
                    ah[mf][1] = Ah[r1 * RS + kk + t];
                    ah[mf][2] = Ah[r0 * RS + kk + t + 4];
                    ah[mf][3] = Ah[r1 * RS + kk + t + 4];
                    am[mf][0] = Am[r0 * RS + kk + t];
                    am[mf][1] = Am[r1 * RS + kk + t];
                    am[mf][2] = Am[r0 * RS + kk + t + 4];
                    am[mf][3] = Am[r1 * RS + kk + t + 4];
                }
                // 3 term passes: each acc touched once per pass (16 apart)
#pragma unroll
                for (int mf = 0; mf < 4; mf++)
#pragma unroll
                    for (int nf = 0; nf < 4; nf++)
                        mma_bf(acc[mf][nf], ah[mf], bh[nf]);
#pragma unroll
                for (int mf = 0; mf < 4; mf++)
#pragma unroll
                    for (int nf = 0; nf < 4; nf++)
                        mma_bf(acc[mf][nf], ah[mf], bm[nf]);
#pragma unroll
                for (int mf = 0; mf < 4; mf++)
#pragma unroll
                    for (int nf = 0; nf < 4; nf++)
                        mma_bf(acc[mf][nf], am[mf], bh[nf]);
            }
            __syncthreads();
        }

        // epilogue: d = ||e||^2 - 2*dot ; per-row top-2 (k ascending)
#pragma unroll
        for (int nf = 0; nf < 4; nf++) {
            int kb = k0 + nw * 32 + nf * 8 + 2 * t;
            float e0 = __ldg(&g_enorm[kb]);
            float e1 = __ldg(&g_enorm[kb + 1]);
#pragma unroll
            for (int mf = 0; mf < 4; mf++) {
#pragma unroll
                for (int h = 0; h < 2; h++) {
                    int rr = mf * 2 + h;
                    float d0 = fmaf(-2.f, acc[mf][nf][h * 2 + 0], e0);
                    float d1 = fmaf(-2.f, acc[mf][nf][h * 2 + 1], e1);
                    if (d0 < m1[rr]) { m2[rr] = m1[rr]; i2[rr] = i1[rr]; m1[rr] = d0; i1[rr] = kb; }
                    else if (d0 < m2[rr]) { m2[rr] = d0; i2[rr] = kb; }
                    if (d1 < m1[rr]) { m2[rr] = m1[rr]; i2[rr] = i1[rr]; m1[rr] = d1; i1[rr] = kb + 1; }
                    else if (d1 < m2[rr]) { m2[rr] = d1; i2[rr] = kb + 1; }
                    acc[mf][nf][h * 2 + 0] = 0.f;
                    acc[mf][nf][h * 2 + 1] = 0.f;
                }
            }
        }
    }

    // merge top-2 across the 4 lanes sharing each row (disjoint code sets)
#pragma unroll
    for (int rr = 0; rr < 8; rr++) {
#pragma unroll
        for (int dd = 1; dd <= 2; dd <<= 1) {
            float n1 = __shfl_xor_sync(0xffffffffu, m1[rr], dd);
            int   j1 = __shfl_xor_sync(0xffffffffu, i1[rr], dd);
            float n2 = __shfl_xor_sync(0xffffffffu, m2[rr], dd);
            int   j2 = __shfl_xor_sync(0xffffffffu, i2[rr], dd);
            if (n1 < m1[rr] || (n1 == m1[rr] && j1 < i1[rr])) {
                m2[rr] = m1[rr]; i2[rr] = i1[rr]; m1[rr] = n1; i1[rr] = j1;
            } else if (n1 < m2[rr] || (n1 == m2[rr] && j1 < i2[rr])) {
                m2[rr] = n1; i2[rr] = j1;
            }
            if (n2 < m2[rr] || (n2 == m2[rr] && j2 < i2[rr])) { m2[rr] = n2; i2[rr] = j2; }
        }
    }

    __syncthreads();
    float4* red = (float4*)sm;   // [64 rows][4 n-warps]
    if (t == 0) {
#pragma unroll
        for (int rr = 0; rr < 8; rr++) {
            int row = (rr >> 1) * 16 + g + 8 * (rr & 1);
            red[row * 4 + nw] = make_float4(m1[rr], __int_as_float(i1[rr]),
                                            m2[rr], __int_as_float(i2[rr]));
        }
    }
    __syncthreads();
    if (tid < MT) {
        float4 v = red[tid * 4 + 0];
        float a1 = v.x; int b1 = __float_as_int(v.y);
        float a2 = v.z; int b2 = __float_as_int(v.w);
#pragma unroll
        for (int w = 1; w < 4; w++) {
            float4 u = red[tid * 4 + w];
            float n1 = u.x; int j1 = __float_as_int(u.y);
            float n2 = u.z; int j2 = __float_as_int(u.w);
            if (n1 < a1 || (n1 == a1 && j1 < b1)) { a2 = a1; b2 = b1; a1 = n1; b1 = j1; }
            else if (n1 < a2 || (n1 == a2 && j1 < b2)) { a2 = n1; b2 = j1; }
            if (n2 < a2 || (n2 == a2 && j2 < b2)) { a2 = n2; b2 = j2; }
        }
        g_cand[(n0 + tid) * 2 + 0] = b1;
        g_cand[(n0 + tid) * 2 + 1] = b2;
    }
}

// ---------------------- exact fp32 rescore of top-2 ------------------------
__global__ void rescore_kernel(const float* __restrict__ emb) {
    int wid = threadIdx.x >> 5, lane = threadIdx.x & 31;
    int n = blockIdx.x * 8 + wid;
    int c1 = g_cand[n * 2], c2 = g_cand[n * 2 + 1];
    const float* zr = g_zT + (size_t)n * C_DIM;
    const float* e1 = emb + (size_t)c1 * C_DIM;
    const float* e2 = emb + (size_t)c2 * C_DIM;
    float s1 = 0.f, s2 = 0.f;
#pragma unroll
    for (int c = lane; c < C_DIM; c += 32) {
        float zv = zr[c];
        float d1 = zv - e1[c], d2 = zv - e2[c];
        s1 += d1 * d1; s2 += d2 * d2;
    }
#pragma unroll
    for (int o = 16; o; o >>= 1) {
        s1 += __shfl_xor_sync(0xffffffffu, s1, o);
        s2 += __shfl_xor_sync(0xffffffffu, s2, o);
    }
    if (lane == 0)
        g_argmin[n] = (s1 < s2 || (s1 == s2 && c1 < c2)) ? c1 : c2;
}

// ------------------------------ gather -------------------------------------
__global__ void gather_kernel(const float* __restrict__ emb,
                              float* __restrict__ out) {
    int t = blockIdx.x * blockDim.x + threadIdx.x;
    int p4 = t & 255;
    int c  = (t >> 8) & 255;
    int b  = t >> 16;
    int nb = b * HW + p4 * 4;
    float4 o;
    o.x = __ldg(&emb[g_argmin[nb + 0] * C_DIM + c]);
    o.y = __ldg(&emb[g_argmin[nb + 1] * C_DIM + c]);
    o.z = __ldg(&emb[g_argmin[nb + 2] * C_DIM + c]);
    o.w = __ldg(&emb[g_argmin[nb + 3] * C_DIM + c]);
    ((float4*)out)[t] = o;
}

// ------------------------------ launch --------------------------------------
extern "C" void kernel_launch(void* const* d_in, const int* in_sizes, int n_in,
                              void* d_out, int out_size) {
    (void)in_sizes; (void)n_in; (void)out_size;
    const float* z   = (const float*)d_in[0];
    const float* emb = (const float*)d_in[1];
    float* out = (float*)d_out;

    cudaFuncSetAttribute(vq_mma_kernel,
                         cudaFuncAttributeMaxDynamicSharedMemorySize, SMEM_BYTES);

    zprep_kernel<<<dim3(HW / 32, C_DIM / 32, 16), dim3(32, 8)>>>(z);
    embprep_kernel<<<(K_CODES * C_DIM) / 256, 256>>>(emb);
    enorm_kernel<<<K_CODES / 8, dim3(32, 8)>>>(emb);
    vq_mma_kernel<<<N_VEC / MT, 128, SMEM_BYTES>>>();
    rescore_kernel<<<N_VEC / 8, 256>>>(emb);
    gather_kernel<<<(N_VEC * C_DIM / 4) / 256, 256>>>(emb, out);
}